// round 14
// baseline (speedup 1.0000x reference)
#include <cuda_runtime.h>
#include <cuda_fp16.h>
#include <math.h>

#define N_NODES 100000
#define IN_DIM 64
#define HALF 32

// ---------------- scratch (device globals: allocation-free) ----------------
__device__ __half g_xT[N_NODES * 64];     // fp16 [x@W1b_agg | x@W1u_agg]
__device__ float4 g_agg1P[N_NODES * 8];   // f32 32-dim agg over pos
__device__ float4 g_agg1N[N_NODES * 8];   // f32 32-dim agg over neg
__device__ __half g_zT[N_NODES * 128];    // fp16 [u | v]
__device__ float4 g_mid[N_NODES * 16];    // outSelf = z_self@W2self + b2
__device__ float4 g_agg2P[N_NODES * 16];  // f32 64-dim agg of u over pos
__device__ float4 g_agg2N[N_NODES * 16];  // f32 64-dim agg of v over neg
__device__ float  g_cntP[N_NODES];
__device__ float  g_cntN[N_NODES];

__device__ __forceinline__ float ftanh(float v) {
    float e = __expf(2.0f * v);
    return 1.0f - 2.0f / (e + 1.0f);
}

// ---------------- layer-1 aggregation: merged pos+neg, fp16 8B gather, one f32 red.v4/thread ----------------
__global__ void __launch_bounds__(256)
agg1_kernel(const int* __restrict__ posSrc, const int* __restrict__ posDst,
            const int* __restrict__ negSrc, const int* __restrict__ negDst, int E)
{
    int t = blockIdx.x * blockDim.x + threadIdx.x;
    if (t >= E * 16) return;
    int isNeg = (t >= E * 8);
    int tt = isNeg ? t - E * 8 : t;
    int e = tt >> 3, c = tt & 7;
    const int* src = isNeg ? negSrc : posSrc;
    const int* dst = isNeg ? negDst : posDst;
    int s = __ldg(src + e);
    int d = __ldg(dst + e);
    uint2 pv = __ldg((const uint2*)(g_xT + s * 64 + isNeg * 32) + c);
    float2 f0 = __half22float2(*(const __half2*)&pv.x);
    float2 f1 = __half22float2(*(const __half2*)&pv.y);
    float* p = (float*)(isNeg ? g_agg1N : g_agg1P) + d * 32 + c * 4;
    asm volatile("red.global.add.v4.f32 [%0], {%1,%2,%3,%4};"
                 :: "l"(p), "f"(f0.x), "f"(f0.y), "f"(f1.x), "f"(f1.y) : "memory");
    if (c == 0) atomicAdd((isNeg ? g_cntN : g_cntP) + d, 1.0f);
}

// ---------------- layer-2 aggregation: merged pos+neg, fp16 8B gather, one f32 red.v4/thread ----------------
__global__ void __launch_bounds__(256)
agg2_kernel(const int* __restrict__ posSrc, const int* __restrict__ posDst,
            const int* __restrict__ negSrc, const int* __restrict__ negDst, int E)
{
    int t = blockIdx.x * blockDim.x + threadIdx.x;
    if (t >= E * 32) return;
    int isNeg = (t >= E * 16);
    int tt = isNeg ? t - E * 16 : t;
    int e = tt >> 4, c = tt & 15;
    const int* src = isNeg ? negSrc : posSrc;
    const int* dst = isNeg ? negDst : posDst;
    int s = __ldg(src + e);
    int d = __ldg(dst + e);
    uint2 pv = __ldg((const uint2*)(g_zT + s * 128 + isNeg * 64) + c);
    float2 f0 = __half22float2(*(const __half2*)&pv.x);
    float2 f1 = __half22float2(*(const __half2*)&pv.y);
    float* p = (float*)(isNeg ? g_agg2N : g_agg2P) + d * 64 + c * 4;
    asm volatile("red.global.add.v4.f32 [%0], {%1,%2,%3,%4};"
                 :: "l"(p), "f"(f0.x), "f"(f0.y), "f"(f1.x), "f"(f1.y) : "memory");
}

// ---------------- transform1: xT = [x@w1b(rows 0:64) | x@w1u(rows 0:64)] (fp16 out) + zero agg1 ----------------
#define KS1 68
__global__ void __launch_bounds__(256, 4)
transform1_kernel(const float* __restrict__ x,
                  const float* __restrict__ w1b, const float* __restrict__ w1u)
{
    __shared__ float sW[2][32][KS1];
    int tid = threadIdx.x;
    for (int i = tid; i < 64 * 32; i += 256) {
        int k = i >> 5, j = i & 31;
        sW[0][j][k] = w1b[i];
        sW[1][j][k] = w1u[i];
    }

    // zero this block's agg1 rows + counts (64 nodes x 8 float4 per buffer)
    int nbase0 = blockIdx.x * 64;
    float4 z4 = make_float4(0.f, 0.f, 0.f, 0.f);
    for (int i = tid; i < 512; i += 256) {
        int idx = nbase0 * 8 + i;
        if (idx < N_NODES * 8) { g_agg1P[idx] = z4; g_agg1N[idx] = z4; }
    }
    if (tid < 64) {
        int n = nbase0 + tid;
        if (n < N_NODES) { g_cntP[n] = 0.f; g_cntN[n] = 0.f; }
    }
    __syncthreads();

    int jg = tid & 15, ng = tid >> 4;
    int branch = jg >> 3, jb = jg & 7;
    int nbase = nbase0 + ng * 4;
    int nidx[4];
    #pragma unroll
    for (int ni = 0; ni < 4; ni++) {
        int n = nbase + ni; if (n > N_NODES - 1) n = N_NODES - 1;
        nidx[ni] = n;
    }

    float acc[4][4];
    #pragma unroll
    for (int ni = 0; ni < 4; ni++)
        #pragma unroll
        for (int o = 0; o < 4; o++) acc[ni][o] = 0.f;

    #pragma unroll 4
    for (int ch = 0; ch < 16; ch++) {
        float4 v[4], w[4];
        #pragma unroll
        for (int ni = 0; ni < 4; ni++)
            v[ni] = __ldg((const float4*)(x + nidx[ni] * 64 + ch * 4));
        #pragma unroll
        for (int o = 0; o < 4; o++)
            w[o] = *(const float4*)&sW[branch][jb + 8 * o][ch * 4];
        #pragma unroll
        for (int ni = 0; ni < 4; ni++)
            #pragma unroll
            for (int o = 0; o < 4; o++) {
                acc[ni][o] = fmaf(v[ni].x, w[o].x, acc[ni][o]);
                acc[ni][o] = fmaf(v[ni].y, w[o].y, acc[ni][o]);
                acc[ni][o] = fmaf(v[ni].z, w[o].z, acc[ni][o]);
                acc[ni][o] = fmaf(v[ni].w, w[o].w, acc[ni][o]);
            }
    }

    #pragma unroll
    for (int ni = 0; ni < 4; ni++) {
        int n = nbase + ni;
        if (n < N_NODES) {
            #pragma unroll
            for (int o = 0; o < 4; o++)
                g_xT[n * 64 + branch * 32 + jb + 8 * o] = __float2half_rn(acc[ni][o]);
        }
    }
}

// ---------------- mid_kernel: fused linear1 + transform2 + linear2-self + zero agg2 ----------------
// Phase A: z = tanh(x@W1self + agg1*inv + b1) -> smem only
// Phase B: zT quadrants (u|v) -> g_zT (fp16);  outSelf = z_self@W2self + b2 -> g_mid
// smem layout (floats): sW1[2*32*68] | sB1[64] | sW2a[2*32*68] | sW2s[2*32*36] | sB2[64] | sZ[64*68]
#define MID_SM_FLOATS (4352 + 64 + 4352 + 2304 + 64 + 4352)
__global__ void __launch_bounds__(256, 3)
mid_kernel(const float* __restrict__ x,
           const float* __restrict__ w1b, const float* __restrict__ b1b,
           const float* __restrict__ w1u, const float* __restrict__ b1u,
           const float* __restrict__ w2b, const float* __restrict__ b2b,
           const float* __restrict__ w2u, const float* __restrict__ b2u)
{
    extern __shared__ float sm[];
    float* sW1  = sm;              // [2][32][68] w1 self rows 64:127
    float* sB1  = sW1 + 4352;
    float* sW2a = sB1 + 64;        // [2][32][68] w2 rows 0:64 (agg part)
    float* sW2s = sW2a + 4352;     // [2][32][36] w2 rows 64:96 (self part)
    float* sB2  = sW2s + 2304;
    float* sZ   = sB2 + 64;        // [64][68]

    int tid = threadIdx.x;
    int nbase = blockIdx.x * 64;

    for (int i = tid; i < 2048; i += 256) {
        int k = i >> 5, j = i & 31;
        sW1[j * 68 + k]         = w1b[2048 + i];
        sW1[2176 + j * 68 + k]  = w1u[2048 + i];
        sW2a[j * 68 + k]        = w2b[i];
        sW2a[2176 + j * 68 + k] = w2u[i];
    }
    for (int i = tid; i < 1024; i += 256) {
        int k = i >> 5, j = i & 31;
        sW2s[j * 36 + k]        = w2b[2048 + i];
        sW2s[1152 + j * 36 + k] = w2u[2048 + i];
    }
    if (tid < 32) {
        sB1[tid] = b1b[tid]; sB1[32 + tid] = b1u[tid];
        sB2[tid] = b2b[tid]; sB2[32 + tid] = b2u[tid];
    }

    // zero this block's agg2 rows (64 nodes x 16 float4 per buffer)
    {
        float4 z4 = make_float4(0.f, 0.f, 0.f, 0.f);
        for (int i = tid; i < 1024; i += 256) {
            int idx = nbase * 16 + i;
            if (idx < N_NODES * 16) { g_agg2P[idx] = z4; g_agg2N[idx] = z4; }
        }
    }
    __syncthreads();

    // -------- Phase A: z into sZ --------
    {
        int jg = tid & 15, ng = tid >> 4;
        int branch = jg >> 3, jb = jg & 7;
        int rbase = ng * 4;
        int nidx[4];
        #pragma unroll
        for (int ni = 0; ni < 4; ni++) {
            int n = nbase + rbase + ni; if (n > N_NODES - 1) n = N_NODES - 1;
            nidx[ni] = n;
        }
        const float* Wb = sW1 + branch * 2176;
        float acc[4][4];
        #pragma unroll
        for (int ni = 0; ni < 4; ni++)
            #pragma unroll
            for (int o = 0; o < 4; o++)
                acc[ni][o] = sB1[branch * 32 + jb + 8 * o];

        #pragma unroll 4
        for (int ch = 0; ch < 16; ch++) {
            float4 v[4], w[4];
            #pragma unroll
            for (int ni = 0; ni < 4; ni++)
                v[ni] = __ldg((const float4*)(x + nidx[ni] * 64 + ch * 4));
            #pragma unroll
            for (int o = 0; o < 4; o++)
                w[o] = *(const float4*)&Wb[(jb + 8 * o) * 68 + ch * 4];
            #pragma unroll
            for (int ni = 0; ni < 4; ni++)
                #pragma unroll
                for (int o = 0; o < 4; o++) {
                    acc[ni][o] = fmaf(v[ni].x, w[o].x, acc[ni][o]);
                    acc[ni][o] = fmaf(v[ni].y, w[o].y, acc[ni][o]);
                    acc[ni][o] = fmaf(v[ni].z, w[o].z, acc[ni][o]);
                    acc[ni][o] = fmaf(v[ni].w, w[o].w, acc[ni][o]);
                }
        }

        const float* agg = branch ? (const float*)g_agg1N : (const float*)g_agg1P;
        const float* cnt = branch ? g_cntN : g_cntP;
        #pragma unroll
        for (int ni = 0; ni < 4; ni++) {
            float inv = 1.0f / fmaxf(cnt[nidx[ni]], 1.0f);
            #pragma unroll
            for (int o = 0; o < 4; o++) {
                float a = __ldg(agg + nidx[ni] * 32 + jb + 8 * o);
                sZ[(rbase + ni) * 68 + branch * 32 + jb + 8 * o] = ftanh(acc[ni][o] + a * inv);
            }
        }
    }
    __syncthreads();

    // -------- Phase B1/B2: zT quadrants over two 32-node halves --------
    {
        int jg = tid & 31, ng = tid >> 5;
        int q = jg >> 3, jb = jg & 7;
        int h  = (q == 1 || q == 2) ? 1 : 0;
        int wb = (q == 0 || q == 2) ? 0 : 1;
        int ro = (q >= 2) ? 32 : 0;
        const float* W = sW2a + wb * 2176;
        #pragma unroll
        for (int hb = 0; hb < 2; hb++) {
            int rbase = hb * 32 + ng * 4;
            float acc[4][4];
            #pragma unroll
            for (int ni = 0; ni < 4; ni++)
                #pragma unroll
                for (int o = 0; o < 4; o++) acc[ni][o] = 0.f;

            #pragma unroll
            for (int ch = 0; ch < 8; ch++) {
                float4 v[4], w[4];
                #pragma unroll
                for (int ni = 0; ni < 4; ni++)
                    v[ni] = *(const float4*)&sZ[(rbase + ni) * 68 + h * 32 + ch * 4];
                #pragma unroll
                for (int o = 0; o < 4; o++)
                    w[o] = *(const float4*)&W[(jb + 8 * o) * 68 + ro + ch * 4];
                #pragma unroll
                for (int ni = 0; ni < 4; ni++)
                    #pragma unroll
                    for (int o = 0; o < 4; o++) {
                        acc[ni][o] = fmaf(v[ni].x, w[o].x, acc[ni][o]);
                        acc[ni][o] = fmaf(v[ni].y, w[o].y, acc[ni][o]);
                        acc[ni][o] = fmaf(v[ni].z, w[o].z, acc[ni][o]);
                        acc[ni][o] = fmaf(v[ni].w, w[o].w, acc[ni][o]);
                    }
            }
            #pragma unroll
            for (int ni = 0; ni < 4; ni++) {
                int n = nbase + rbase + ni;
                if (n < N_NODES) {
                    #pragma unroll
                    for (int o = 0; o < 4; o++)
                        g_zT[n * 128 + q * 32 + jb + 8 * o] = __float2half_rn(acc[ni][o]);
                }
            }
        }
    }

    // -------- Phase B3: outSelf = z_self@W2self + b2 --------
    {
        int jg = tid & 15, ng = tid >> 4;
        int branch = jg >> 3, jb = jg & 7;
        int rbase = ng * 4;
        const float* W = sW2s + branch * 1152;
        float acc[4][4];
        #pragma unroll
        for (int ni = 0; ni < 4; ni++)
            #pragma unroll
            for (int o = 0; o < 4; o++)
                acc[ni][o] = sB2[branch * 32 + jb + 8 * o];

        #pragma unroll
        for (int ch = 0; ch < 8; ch++) {
            float4 v[4], w[4];
            #pragma unroll
            for (int ni = 0; ni < 4; ni++)
                v[ni] = *(const float4*)&sZ[(rbase + ni) * 68 + branch * 32 + ch * 4];
            #pragma unroll
            for (int o = 0; o < 4; o++)
                w[o] = *(const float4*)&W[(jb + 8 * o) * 36 + ch * 4];
            #pragma unroll
            for (int ni = 0; ni < 4; ni++)
                #pragma unroll
                for (int o = 0; o < 4; o++) {
                    acc[ni][o] = fmaf(v[ni].x, w[o].x, acc[ni][o]);
                    acc[ni][o] = fmaf(v[ni].y, w[o].y, acc[ni][o]);
                    acc[ni][o] = fmaf(v[ni].z, w[o].z, acc[ni][o]);
                    acc[ni][o] = fmaf(v[ni].w, w[o].w, acc[ni][o]);
                }
        }
        float* midF = (float*)g_mid;
        #pragma unroll
        for (int ni = 0; ni < 4; ni++) {
            int n = nbase + rbase + ni;
            if (n < N_NODES) {
                #pragma unroll
                for (int o = 0; o < 4; o++)
                    midF[n * 64 + branch * 32 + jb + 8 * o] = acc[ni][o];
            }
        }
    }
}

// ---------------- epilogue: out = tanh(outSelf + agg2P*invP + agg2N*invN) ----------------
__global__ void __launch_bounds__(256)
epilogue_kernel(float4* __restrict__ out)
{
    int i = blockIdx.x * blockDim.x + threadIdx.x;
    if (i >= N_NODES * 16) return;
    int n = i >> 4;
    float invP = 1.0f / fmaxf(g_cntP[n], 1.0f);
    float invN = 1.0f / fmaxf(g_cntN[n], 1.0f);
    float4 m = g_mid[i];
    float4 u = g_agg2P[i];
    float4 v = g_agg2N[i];
    float4 r;
    r.x = ftanh(m.x + u.x * invP + v.x * invN);
    r.y = ftanh(m.y + u.y * invP + v.y * invN);
    r.z = ftanh(m.z + u.z * invP + v.z * invN);
    r.w = ftanh(m.w + u.w * invP + v.w * invN);
    out[i] = r;
}

// ---------------- launch ----------------
extern "C" void kernel_launch(void* const* d_in, const int* in_sizes, int n_in,
                              void* d_out, int out_size)
{
    const float* x    = (const float*)d_in[0];
    const int* posEI  = (const int*)d_in[1];
    const int* negEI  = (const int*)d_in[2];
    const float* w1b  = (const float*)d_in[3];
    const float* b1b  = (const float*)d_in[4];
    const float* w1u  = (const float*)d_in[5];
    const float* b1u  = (const float*)d_in[6];
    const float* w2b  = (const float*)d_in[7];
    const float* b2b  = (const float*)d_in[8];
    const float* w2u  = (const float*)d_in[9];
    const float* b2u  = (const float*)d_in[10];
    float* out = (float*)d_out;

    int E = in_sizes[1] / 2;             // 1,600,000
    const int* posSrc = posEI;
    const int* posDst = posEI + E;
    const int* negSrc = negEI;
    const int* negDst = negEI + E;

    int agg1Grid  = (E * 16 + 255) / 256;   // pos+neg merged
    int agg2Grid  = (E * 32 + 255) / 256;   // pos+neg merged
    int lin64Grid = (N_NODES + 63) / 64;    // 1563
    int epiGrid   = (N_NODES * 16 + 255) / 256;

    int midSm = MID_SM_FLOATS * 4;          // 61,952 bytes
    cudaFuncSetAttribute(mid_kernel, cudaFuncAttributeMaxDynamicSharedMemorySize, midSm);

    // --- layer 1 ---
    transform1_kernel<<<lin64Grid, 256>>>(x, w1b, w1u);
    agg1_kernel<<<agg1Grid, 256>>>(posSrc, posDst, negSrc, negDst, E);

    // --- fused mid-section ---
    mid_kernel<<<lin64Grid, 256, midSm>>>(x, w1b, b1b, w1u, b1u, w2b, b2b, w2u, b2u);

    // --- layer 2 ---
    agg2_kernel<<<agg2Grid, 256>>>(posSrc, posDst, negSrc, negDst, E);
    epilogue_kernel<<<epiGrid, 256>>>((float4*)out);
}

// round 15
// speedup vs baseline: 1.3011x; 1.3011x over previous
#include <cuda_runtime.h>
#include <cuda_fp16.h>
#include <math.h>

#define N_NODES 100000
#define IN_DIM 64
#define HALF 32

// ---------------- scratch (device globals: allocation-free) ----------------
__device__ __half g_xT[N_NODES * 64];     // fp16 [x@W1b_agg | x@W1u_agg]
__device__ float4 g_agg1P[N_NODES * 8];   // f32 32-dim agg over pos
__device__ float4 g_agg1N[N_NODES * 8];   // f32 32-dim agg over neg
__device__ float4 g_z[N_NODES * 16];      // layer-1 output, f32
__device__ __half g_zT[N_NODES * 128];    // fp16 [u | v]
__device__ __half g_agg2P[N_NODES * 64];  // fp16 64-dim agg of u over pos
__device__ __half g_agg2N[N_NODES * 64];  // fp16 64-dim agg of v over neg
__device__ float  g_cntP[N_NODES];
__device__ float  g_cntN[N_NODES];

__device__ __forceinline__ float ftanh(float v) {
    float e = __expf(2.0f * v);
    return 1.0f - 2.0f / (e + 1.0f);
}

// ---------------- layer-1 aggregation: merged pos+neg, fp16 8B gather, one f32 red.v4/thread ----------------
__global__ void __launch_bounds__(256)
agg1_kernel(const int* __restrict__ posSrc, const int* __restrict__ posDst,
            const int* __restrict__ negSrc, const int* __restrict__ negDst, int E)
{
    int t = blockIdx.x * blockDim.x + threadIdx.x;
    if (t >= E * 16) return;
    int isNeg = (t >= E * 8);
    int tt = isNeg ? t - E * 8 : t;
    int e = tt >> 3, c = tt & 7;
    const int* src = isNeg ? negSrc : posSrc;
    const int* dst = isNeg ? negDst : posDst;
    int s = __ldg(src + e);
    int d = __ldg(dst + e);
    uint2 pv = __ldg((const uint2*)(g_xT + s * 64 + isNeg * 32) + c);
    float2 f0 = __half22float2(*(const __half2*)&pv.x);
    float2 f1 = __half22float2(*(const __half2*)&pv.y);
    float* p = (float*)(isNeg ? g_agg1N : g_agg1P) + d * 32 + c * 4;
    asm volatile("red.global.add.v4.f32 [%0], {%1,%2,%3,%4};"
                 :: "l"(p), "f"(f0.x), "f"(f0.y), "f"(f1.x), "f"(f1.y) : "memory");
    if (c == 0) atomicAdd((isNeg ? g_cntN : g_cntP) + d, 1.0f);
}

// ---------------- layer-2 aggregation: merged pos+neg, fp16 16B gather, one fp16x2 red.v4/thread ----------------
// 8 threads/edge, each handles 8 dims: load uint4 of fp16 and red directly (no conversion).
__global__ void __launch_bounds__(256)
agg2_kernel(const int* __restrict__ posSrc, const int* __restrict__ posDst,
            const int* __restrict__ negSrc, const int* __restrict__ negDst, int E)
{
    int t = blockIdx.x * blockDim.x + threadIdx.x;
    if (t >= E * 16) return;
    int isNeg = (t >= E * 8);
    int tt = isNeg ? t - E * 8 : t;
    int e = tt >> 3, c = tt & 7;
    const int* src = isNeg ? negSrc : posSrc;
    const int* dst = isNeg ? negDst : posDst;
    int s = __ldg(src + e);
    int d = __ldg(dst + e);
    uint4 pv = __ldg((const uint4*)(g_zT + s * 128 + isNeg * 64) + c);
    __half* p = (isNeg ? g_agg2N : g_agg2P) + d * 64 + c * 8;
    asm volatile("red.global.add.noftz.v4.f16x2 [%0], {%1,%2,%3,%4};"
                 :: "l"(p), "r"(pv.x), "r"(pv.y), "r"(pv.z), "r"(pv.w) : "memory");
}

// ---------------- transform1: xT = [x@w1b(rows 0:64) | x@w1u(rows 0:64)] (fp16 out) + zero agg1 ----------------
#define KS1 68
__global__ void __launch_bounds__(256, 4)
transform1_kernel(const float* __restrict__ x,
                  const float* __restrict__ w1b, const float* __restrict__ w1u)
{
    __shared__ float sW[2][32][KS1];
    int tid = threadIdx.x;
    for (int i = tid; i < 64 * 32; i += 256) {
        int k = i >> 5, j = i & 31;
        sW[0][j][k] = w1b[i];
        sW[1][j][k] = w1u[i];
    }

    // zero this block's agg1 rows + counts (64 nodes x 8 float4 per buffer)
    int nbase0 = blockIdx.x * 64;
    float4 z4 = make_float4(0.f, 0.f, 0.f, 0.f);
    for (int i = tid; i < 512; i += 256) {
        int idx = nbase0 * 8 + i;
        if (idx < N_NODES * 8) { g_agg1P[idx] = z4; g_agg1N[idx] = z4; }
    }
    if (tid < 64) {
        int n = nbase0 + tid;
        if (n < N_NODES) { g_cntP[n] = 0.f; g_cntN[n] = 0.f; }
    }
    __syncthreads();

    int jg = tid & 15, ng = tid >> 4;
    int branch = jg >> 3, jb = jg & 7;
    int nbase = nbase0 + ng * 4;
    int nidx[4];
    #pragma unroll
    for (int ni = 0; ni < 4; ni++) {
        int n = nbase + ni; if (n > N_NODES - 1) n = N_NODES - 1;
        nidx[ni] = n;
    }

    float acc[4][4];
    #pragma unroll
    for (int ni = 0; ni < 4; ni++)
        #pragma unroll
        for (int o = 0; o < 4; o++) acc[ni][o] = 0.f;

    #pragma unroll 4
    for (int ch = 0; ch < 16; ch++) {
        float4 v[4], w[4];
        #pragma unroll
        for (int ni = 0; ni < 4; ni++)
            v[ni] = __ldg((const float4*)(x + nidx[ni] * 64 + ch * 4));
        #pragma unroll
        for (int o = 0; o < 4; o++)
            w[o] = *(const float4*)&sW[branch][jb + 8 * o][ch * 4];
        #pragma unroll
        for (int ni = 0; ni < 4; ni++)
            #pragma unroll
            for (int o = 0; o < 4; o++) {
                acc[ni][o] = fmaf(v[ni].x, w[o].x, acc[ni][o]);
                acc[ni][o] = fmaf(v[ni].y, w[o].y, acc[ni][o]);
                acc[ni][o] = fmaf(v[ni].z, w[o].z, acc[ni][o]);
                acc[ni][o] = fmaf(v[ni].w, w[o].w, acc[ni][o]);
            }
    }

    #pragma unroll
    for (int ni = 0; ni < 4; ni++) {
        int n = nbase + ni;
        if (n < N_NODES) {
            #pragma unroll
            for (int o = 0; o < 4; o++)
                g_xT[n * 64 + branch * 32 + jb + 8 * o] = __float2half_rn(acc[ni][o]);
        }
    }
}

// ---------------- linear1: z = tanh(agg1*inv + x@Wself + b) ----------------
__global__ void __launch_bounds__(256, 4)
linear1_lite(const float* __restrict__ x,
             const float* __restrict__ w1b, const float* __restrict__ b1b,
             const float* __restrict__ w1u, const float* __restrict__ b1u)
{
    __shared__ float sW[2][32][KS1];   // self rows 64:127
    __shared__ float sB[64];
    int tid = threadIdx.x;
    for (int i = tid; i < 64 * 32; i += 256) {
        int k = i >> 5, j = i & 31;
        sW[0][j][k] = w1b[2048 + i];
        sW[1][j][k] = w1u[2048 + i];
    }
    if (tid < 32) { sB[tid] = b1b[tid]; sB[tid + 32] = b1u[tid]; }
    __syncthreads();

    int jg = tid & 15, ng = tid >> 4;
    int branch = jg >> 3, jb = jg & 7;
    int nbase = blockIdx.x * 64 + ng * 4;
    int nidx[4];
    #pragma unroll
    for (int ni = 0; ni < 4; ni++) {
        int n = nbase + ni; if (n > N_NODES - 1) n = N_NODES - 1;
        nidx[ni] = n;
    }

    float acc[4][4];
    #pragma unroll
    for (int ni = 0; ni < 4; ni++)
        #pragma unroll
        for (int o = 0; o < 4; o++)
            acc[ni][o] = sB[branch * 32 + jb + 8 * o];

    #pragma unroll 4
    for (int ch = 0; ch < 16; ch++) {
        float4 v[4], w[4];
        #pragma unroll
        for (int ni = 0; ni < 4; ni++)
            v[ni] = __ldg((const float4*)(x + nidx[ni] * 64 + ch * 4));
        #pragma unroll
        for (int o = 0; o < 4; o++)
            w[o] = *(const float4*)&sW[branch][jb + 8 * o][ch * 4];
        #pragma unroll
        for (int ni = 0; ni < 4; ni++)
            #pragma unroll
            for (int o = 0; o < 4; o++) {
                acc[ni][o] = fmaf(v[ni].x, w[o].x, acc[ni][o]);
                acc[ni][o] = fmaf(v[ni].y, w[o].y, acc[ni][o]);
                acc[ni][o] = fmaf(v[ni].z, w[o].z, acc[ni][o]);
                acc[ni][o] = fmaf(v[ni].w, w[o].w, acc[ni][o]);
            }
    }

    const float* agg = branch ? (const float*)g_agg1N : (const float*)g_agg1P;
    const float* cnt = branch ? g_cntN : g_cntP;
    float* zout = (float*)g_z;
    #pragma unroll
    for (int ni = 0; ni < 4; ni++) {
        int n = nbase + ni;
        if (n < N_NODES) {
            float inv = 1.0f / fmaxf(cnt[n], 1.0f);
            #pragma unroll
            for (int o = 0; o < 4; o++) {
                float a = __ldg(agg + n * 32 + jb + 8 * o);
                zout[n * 64 + branch * 32 + jb + 8 * o] = ftanh(acc[ni][o] + a * inv);
            }
        }
    }
}

// ---------------- transform2: zT = [u | v] (fp16 out) + zero agg2 (fp16) ----------------
// u[0:32]=zp@w2b[0:32]   u[32:64]=zn@w2u[0:32]
// v[0:32]=zn@w2b[32:64]  v[32:64]=zp@w2u[32:64]
__global__ void __launch_bounds__(256, 4)
transform2_kernel(const float* __restrict__ w2b, const float* __restrict__ w2u)
{
    __shared__ float sW[2][32][KS1];   // w2b/w2u rows 0:64
    int tid = threadIdx.x;
    for (int i = tid; i < 64 * 32; i += 256) {
        int k = i >> 5, j = i & 31;
        sW[0][j][k] = w2b[i];
        sW[1][j][k] = w2u[i];
    }

    // zero this block's agg2 rows (32 nodes x 64 halfs = 256 uint4 per buffer)
    int nbase0 = blockIdx.x * 32;
    uint4 z4 = make_uint4(0u, 0u, 0u, 0u);
    for (int i = tid; i < 256; i += 256) ;  // placeholder to keep structure clear
    for (int i = tid; i < 256; i += 256) {
        int idx = nbase0 * 8 + i;
        if (idx < N_NODES * 8) {
            ((uint4*)g_agg2P)[idx] = z4;
            ((uint4*)g_agg2N)[idx] = z4;
        }
    }
    __syncthreads();

    int jg = tid & 31, ng = tid >> 5;
    int q = jg >> 3, jb = jg & 7;
    int h  = (q == 1 || q == 2) ? 1 : 0;
    int wb = (q == 0 || q == 2) ? 0 : 1;
    int ro = (q >= 2) ? 32 : 0;
    int nbase = nbase0 + ng * 4;
    int nidx[4];
    #pragma unroll
    for (int ni = 0; ni < 4; ni++) {
        int n = nbase + ni; if (n > N_NODES - 1) n = N_NODES - 1;
        nidx[ni] = n;
    }

    const float* z = (const float*)g_z;
    float acc[4][4];
    #pragma unroll
    for (int ni = 0; ni < 4; ni++)
        #pragma unroll
        for (int o = 0; o < 4; o++) acc[ni][o] = 0.f;

    #pragma unroll
    for (int ch = 0; ch < 8; ch++) {
        float4 v[4], w[4];
        #pragma unroll
        for (int ni = 0; ni < 4; ni++)
            v[ni] = __ldg((const float4*)(z + nidx[ni] * 64 + h * 32 + ch * 4));
        #pragma unroll
        for (int o = 0; o < 4; o++)
            w[o] = *(const float4*)&sW[wb][jb + 8 * o][ro + ch * 4];
        #pragma unroll
        for (int ni = 0; ni < 4; ni++)
            #pragma unroll
            for (int o = 0; o < 4; o++) {
                acc[ni][o] = fmaf(v[ni].x, w[o].x, acc[ni][o]);
                acc[ni][o] = fmaf(v[ni].y, w[o].y, acc[ni][o]);
                acc[ni][o] = fmaf(v[ni].z, w[o].z, acc[ni][o]);
                acc[ni][o] = fmaf(v[ni].w, w[o].w, acc[ni][o]);
            }
    }

    #pragma unroll
    for (int ni = 0; ni < 4; ni++) {
        int n = nbase + ni;
        if (n < N_NODES) {
            #pragma unroll
            for (int o = 0; o < 4; o++)
                g_zT[n * 128 + q * 32 + jb + 8 * o] = __float2half_rn(acc[ni][o]);
        }
    }
}

// ---------------- linear2: out = tanh(agg2P*invP + agg2N*invN + z_self@Wself + b) ----------------
#define KS2 36
__global__ void __launch_bounds__(256, 4)
linear2_lite(const float* __restrict__ w2b, const float* __restrict__ b2b,
             const float* __restrict__ w2u, const float* __restrict__ b2u,
             float* __restrict__ out)
{
    __shared__ float sW[2][32][KS2];   // self rows 64:95
    __shared__ float sB[64];
    int tid = threadIdx.x;
    for (int i = tid; i < 32 * 32; i += 256) {
        int k = i >> 5, j = i & 31;
        sW[0][j][k] = w2b[2048 + i];
        sW[1][j][k] = w2u[2048 + i];
    }
    if (tid < 32) { sB[tid] = b2b[tid]; sB[tid + 32] = b2u[tid]; }
    __syncthreads();

    int jg = tid & 15, ng = tid >> 4;
    int branch = jg >> 3, jb = jg & 7;
    int nbase = blockIdx.x * 64 + ng * 4;
    int nidx[4];
    #pragma unroll
    for (int ni = 0; ni < 4; ni++) {
        int n = nbase + ni; if (n > N_NODES - 1) n = N_NODES - 1;
        nidx[ni] = n;
    }

    const float* z = (const float*)g_z;
    float acc[4][4];
    #pragma unroll
    for (int ni = 0; ni < 4; ni++)
        #pragma unroll
        for (int o = 0; o < 4; o++)
            acc[ni][o] = sB[branch * 32 + jb + 8 * o];

    #pragma unroll
    for (int ch = 0; ch < 8; ch++) {
        float4 v[4], w[4];
        #pragma unroll
        for (int ni = 0; ni < 4; ni++)
            v[ni] = __ldg((const float4*)(z + nidx[ni] * 64 + branch * 32 + ch * 4));
        #pragma unroll
        for (int o = 0; o < 4; o++)
            w[o] = *(const float4*)&sW[branch][jb + 8 * o][ch * 4];
        #pragma unroll
        for (int ni = 0; ni < 4; ni++)
            #pragma unroll
            for (int o = 0; o < 4; o++) {
                acc[ni][o] = fmaf(v[ni].x, w[o].x, acc[ni][o]);
                acc[ni][o] = fmaf(v[ni].y, w[o].y, acc[ni][o]);
                acc[ni][o] = fmaf(v[ni].z, w[o].z, acc[ni][o]);
                acc[ni][o] = fmaf(v[ni].w, w[o].w, acc[ni][o]);
            }
    }

    #pragma unroll
    for (int ni = 0; ni < 4; ni++) {
        int n = nbase + ni;
        if (n < N_NODES) {
            float invP = 1.0f / fmaxf(g_cntP[n], 1.0f);
            float invN = 1.0f / fmaxf(g_cntN[n], 1.0f);
            #pragma unroll
            for (int o = 0; o < 4; o++) {
                int j = branch * 32 + jb + 8 * o;
                float au = __half2float(g_agg2P[n * 64 + j]);
                float av = __half2float(g_agg2N[n * 64 + j]);
                out[n * 64 + j] = ftanh(acc[ni][o] + au * invP + av * invN);
            }
        }
    }
}

// ---------------- launch ----------------
extern "C" void kernel_launch(void* const* d_in, const int* in_sizes, int n_in,
                              void* d_out, int out_size)
{
    const float* x    = (const float*)d_in[0];
    const int* posEI  = (const int*)d_in[1];
    const int* negEI  = (const int*)d_in[2];
    const float* w1b  = (const float*)d_in[3];
    const float* b1b  = (const float*)d_in[4];
    const float* w1u  = (const float*)d_in[5];
    const float* b1u  = (const float*)d_in[6];
    const float* w2b  = (const float*)d_in[7];
    const float* b2b  = (const float*)d_in[8];
    const float* w2u  = (const float*)d_in[9];
    const float* b2u  = (const float*)d_in[10];
    float* out = (float*)d_out;

    int E = in_sizes[1] / 2;             // 1,600,000
    const int* posSrc = posEI;
    const int* posDst = posEI + E;
    const int* negSrc = negEI;
    const int* negDst = negEI + E;

    int agg1Grid  = (E * 16 + 255) / 256;   // pos+neg merged
    int agg2Grid  = (E * 16 + 255) / 256;   // pos+neg merged, 8 threads/edge
    int lin64Grid = (N_NODES + 63) / 64;    // 1563
    int lin32Grid = (N_NODES + 31) / 32;    // 3125

    // --- layer 1 ---
    transform1_kernel<<<lin64Grid, 256>>>(x, w1b, w1u);
    agg1_kernel<<<agg1Grid, 256>>>(posSrc, posDst, negSrc, negDst, E);
    linear1_lite<<<lin64Grid, 256>>>(x, w1b, b1b, w1u, b1u);

    // --- layer 2 ---
    transform2_kernel<<<lin32Grid, 256>>>(w2b, w2u);
    agg2_kernel<<<agg2Grid, 256>>>(posSrc, posDst, negSrc, negDst, E);
    linear2_lite<<<lin64Grid, 256>>>(w2b, b2b, w2u, b2u, out);
}

// round 16
// speedup vs baseline: 1.3077x; 1.0050x over previous
#include <cuda_runtime.h>
#include <cuda_fp16.h>
#include <math.h>

#define N_NODES 100000
#define IN_DIM 64
#define HALF 32

// ---------------- scratch (device globals: allocation-free) ----------------
__device__ __half g_xT[N_NODES * 64];     // fp16 [x@W1b_agg | x@W1u_agg]
__device__ float4 g_agg1P[N_NODES * 8];   // f32 32-dim agg over pos
__device__ float4 g_agg1N[N_NODES * 8];   // f32 32-dim agg over neg
__device__ float4 g_z[N_NODES * 16];      // layer-1 output, f32
__device__ __half g_zT[N_NODES * 128];    // fp16 [u | v]
__device__ __half g_agg2P[N_NODES * 64];  // fp16 64-dim agg of u over pos
__device__ __half g_agg2N[N_NODES * 64];  // fp16 64-dim agg of v over neg
__device__ float  g_cntP[N_NODES];
__device__ float  g_cntN[N_NODES];

__device__ __forceinline__ float ftanh(float v) {
    float e = __expf(2.0f * v);
    return 1.0f - 2.0f / (e + 1.0f);
}

// ---------------- layer-1 aggregation: merged pos+neg, fp16 8B gather, one f32 red.v4/thread ----------------
__global__ void __launch_bounds__(256)
agg1_kernel(const int* __restrict__ posSrc, const int* __restrict__ posDst,
            const int* __restrict__ negSrc, const int* __restrict__ negDst, int E)
{
    int t = blockIdx.x * blockDim.x + threadIdx.x;
    if (t >= E * 16) return;
    int isNeg = (t >= E * 8);
    int tt = isNeg ? t - E * 8 : t;
    int e = tt >> 3, c = tt & 7;
    const int* src = isNeg ? negSrc : posSrc;
    const int* dst = isNeg ? negDst : posDst;
    int s = __ldg(src + e);
    int d = __ldg(dst + e);
    uint2 pv = __ldg((const uint2*)(g_xT + s * 64 + isNeg * 32) + c);
    float2 f0 = __half22float2(*(const __half2*)&pv.x);
    float2 f1 = __half22float2(*(const __half2*)&pv.y);
    float* p = (float*)(isNeg ? g_agg1N : g_agg1P) + d * 32 + c * 4;
    asm volatile("red.global.add.v4.f32 [%0], {%1,%2,%3,%4};"
                 :: "l"(p), "f"(f0.x), "f"(f0.y), "f"(f1.x), "f"(f1.y) : "memory");
    if (c == 0) atomicAdd((isNeg ? g_cntN : g_cntP) + d, 1.0f);
}

// ---------------- layer-2 aggregation: merged pos+neg, fp16 16B gather, one fp16x2 red.v4/thread ----------------
// 8 threads/edge, each handles 8 dims: load uint4 of fp16 and red directly (no conversion).
__global__ void __launch_bounds__(256)
agg2_kernel(const int* __restrict__ posSrc, const int* __restrict__ posDst,
            const int* __restrict__ negSrc, const int* __restrict__ negDst, int E)
{
    int t = blockIdx.x * blockDim.x + threadIdx.x;
    if (t >= E * 16) return;
    int isNeg = (t >= E * 8);
    int tt = isNeg ? t - E * 8 : t;
    int e = tt >> 3, c = tt & 7;
    const int* src = isNeg ? negSrc : posSrc;
    const int* dst = isNeg ? negDst : posDst;
    int s = __ldg(src + e);
    int d = __ldg(dst + e);
    uint4 pv = __ldg((const uint4*)(g_zT + s * 128 + isNeg * 64) + c);
    __half* p = (isNeg ? g_agg2N : g_agg2P) + d * 64 + c * 8;
    asm volatile("red.global.add.noftz.v4.f16x2 [%0], {%1,%2,%3,%4};"
                 :: "l"(p), "r"(pv.x), "r"(pv.y), "r"(pv.z), "r"(pv.w) : "memory");
}

// ---------------- transform1: xT = [x@w1b(rows 0:64) | x@w1u(rows 0:64)] (fp16 out) + zero agg1 ----------------
#define KS1 68
__global__ void __launch_bounds__(256, 4)
transform1_kernel(const float* __restrict__ x,
                  const float* __restrict__ w1b, const float* __restrict__ w1u)
{
    __shared__ float sW[2][32][KS1];
    int tid = threadIdx.x;
    for (int i = tid; i < 64 * 32; i += 256) {
        int k = i >> 5, j = i & 31;
        sW[0][j][k] = w1b[i];
        sW[1][j][k] = w1u[i];
    }

    // zero this block's agg1 rows + counts (64 nodes x 8 float4 per buffer)
    int nbase0 = blockIdx.x * 64;
    float4 z4 = make_float4(0.f, 0.f, 0.f, 0.f);
    for (int i = tid; i < 512; i += 256) {
        int idx = nbase0 * 8 + i;
        if (idx < N_NODES * 8) { g_agg1P[idx] = z4; g_agg1N[idx] = z4; }
    }
    if (tid < 64) {
        int n = nbase0 + tid;
        if (n < N_NODES) { g_cntP[n] = 0.f; g_cntN[n] = 0.f; }
    }
    __syncthreads();

    int jg = tid & 15, ng = tid >> 4;
    int branch = jg >> 3, jb = jg & 7;
    int nbase = nbase0 + ng * 4;
    int nidx[4];
    #pragma unroll
    for (int ni = 0; ni < 4; ni++) {
        int n = nbase + ni; if (n > N_NODES - 1) n = N_NODES - 1;
        nidx[ni] = n;
    }

    float acc[4][4];
    #pragma unroll
    for (int ni = 0; ni < 4; ni++)
        #pragma unroll
        for (int o = 0; o < 4; o++) acc[ni][o] = 0.f;

    #pragma unroll 4
    for (int ch = 0; ch < 16; ch++) {
        float4 v[4], w[4];
        #pragma unroll
        for (int ni = 0; ni < 4; ni++)
            v[ni] = __ldg((const float4*)(x + nidx[ni] * 64 + ch * 4));
        #pragma unroll
        for (int o = 0; o < 4; o++)
            w[o] = *(const float4*)&sW[branch][jb + 8 * o][ch * 4];
        #pragma unroll
        for (int ni = 0; ni < 4; ni++)
            #pragma unroll
            for (int o = 0; o < 4; o++) {
                acc[ni][o] = fmaf(v[ni].x, w[o].x, acc[ni][o]);
                acc[ni][o] = fmaf(v[ni].y, w[o].y, acc[ni][o]);
                acc[ni][o] = fmaf(v[ni].z, w[o].z, acc[ni][o]);
                acc[ni][o] = fmaf(v[ni].w, w[o].w, acc[ni][o]);
            }
    }

    #pragma unroll
    for (int ni = 0; ni < 4; ni++) {
        int n = nbase + ni;
        if (n < N_NODES) {
            #pragma unroll
            for (int o = 0; o < 4; o++)
                g_xT[n * 64 + branch * 32 + jb + 8 * o] = __float2half_rn(acc[ni][o]);
        }
    }
}

// ---------------- linear1: z = tanh(agg1*inv + x@Wself + b) ----------------
__global__ void __launch_bounds__(256, 4)
linear1_lite(const float* __restrict__ x,
             const float* __restrict__ w1b, const float* __restrict__ b1b,
             const float* __restrict__ w1u, const float* __restrict__ b1u)
{
    __shared__ float sW[2][32][KS1];   // self rows 64:127
    __shared__ float sB[64];
    int tid = threadIdx.x;
    for (int i = tid; i < 64 * 32; i += 256) {
        int k = i >> 5, j = i & 31;
        sW[0][j][k] = w1b[2048 + i];
        sW[1][j][k] = w1u[2048 + i];
    }
    if (tid < 32) { sB[tid] = b1b[tid]; sB[tid + 32] = b1u[tid]; }
    __syncthreads();

    int jg = tid & 15, ng = tid >> 4;
    int branch = jg >> 3, jb = jg & 7;
    int nbase = blockIdx.x * 64 + ng * 4;
    int nidx[4];
    #pragma unroll
    for (int ni = 0; ni < 4; ni++) {
        int n = nbase + ni; if (n > N_NODES - 1) n = N_NODES - 1;
        nidx[ni] = n;
    }

    float acc[4][4];
    #pragma unroll
    for (int ni = 0; ni < 4; ni++)
        #pragma unroll
        for (int o = 0; o < 4; o++)
            acc[ni][o] = sB[branch * 32 + jb + 8 * o];

    #pragma unroll 4
    for (int ch = 0; ch < 16; ch++) {
        float4 v[4], w[4];
        #pragma unroll
        for (int ni = 0; ni < 4; ni++)
            v[ni] = __ldg((const float4*)(x + nidx[ni] * 64 + ch * 4));
        #pragma unroll
        for (int o = 0; o < 4; o++)
            w[o] = *(const float4*)&sW[branch][jb + 8 * o][ch * 4];
        #pragma unroll
        for (int ni = 0; ni < 4; ni++)
            #pragma unroll
            for (int o = 0; o < 4; o++) {
                acc[ni][o] = fmaf(v[ni].x, w[o].x, acc[ni][o]);
                acc[ni][o] = fmaf(v[ni].y, w[o].y, acc[ni][o]);
                acc[ni][o] = fmaf(v[ni].z, w[o].z, acc[ni][o]);
                acc[ni][o] = fmaf(v[ni].w, w[o].w, acc[ni][o]);
            }
    }

    const float* agg = branch ? (const float*)g_agg1N : (const float*)g_agg1P;
    const float* cnt = branch ? g_cntN : g_cntP;
    float* zout = (float*)g_z;
    #pragma unroll
    for (int ni = 0; ni < 4; ni++) {
        int n = nbase + ni;
        if (n < N_NODES) {
            float inv = 1.0f / fmaxf(cnt[n], 1.0f);
            #pragma unroll
            for (int o = 0; o < 4; o++) {
                float a = __ldg(agg + n * 32 + jb + 8 * o);
                zout[n * 64 + branch * 32 + jb + 8 * o] = ftanh(acc[ni][o] + a * inv);
            }
        }
    }
}

// ---------------- transform2: zT = [u | v] (fp16 out) + zero agg2 (fp16) ----------------
// u[0:32]=zp@w2b[0:32]   u[32:64]=zn@w2u[0:32]
// v[0:32]=zn@w2b[32:64]  v[32:64]=zp@w2u[32:64]
__global__ void __launch_bounds__(256, 4)
transform2_kernel(const float* __restrict__ w2b, const float* __restrict__ w2u)
{
    __shared__ float sW[2][32][KS1];   // w2b/w2u rows 0:64
    int tid = threadIdx.x;
    for (int i = tid; i < 64 * 32; i += 256) {
        int k = i >> 5, j = i & 31;
        sW[0][j][k] = w2b[i];
        sW[1][j][k] = w2u[i];
    }

    // zero this block's agg2 rows (32 nodes x 64 halfs = 256 uint4 per buffer)
    int nbase0 = blockIdx.x * 32;
    uint4 z4 = make_uint4(0u, 0u, 0u, 0u);
    for (int i = tid; i < 256; i += 256) ;  // placeholder to keep structure clear
    for (int i = tid; i < 256; i += 256) {
        int idx = nbase0 * 8 + i;
        if (idx < N_NODES * 8) {
            ((uint4*)g_agg2P)[idx] = z4;
            ((uint4*)g_agg2N)[idx] = z4;
        }
    }
    __syncthreads();

    int jg = tid & 31, ng = tid >> 5;
    int q = jg >> 3, jb = jg & 7;
    int h  = (q == 1 || q == 2) ? 1 : 0;
    int wb = (q == 0 || q == 2) ? 0 : 1;
    int ro = (q >= 2) ? 32 : 0;
    int nbase = nbase0 + ng * 4;
    int nidx[4];
    #pragma unroll
    for (int ni = 0; ni < 4; ni++) {
        int n = nbase + ni; if (n > N_NODES - 1) n = N_NODES - 1;
        nidx[ni] = n;
    }

    const float* z = (const float*)g_z;
    float acc[4][4];
    #pragma unroll
    for (int ni = 0; ni < 4; ni++)
        #pragma unroll
        for (int o = 0; o < 4; o++) acc[ni][o] = 0.f;

    #pragma unroll
    for (int ch = 0; ch < 8; ch++) {
        float4 v[4], w[4];
        #pragma unroll
        for (int ni = 0; ni < 4; ni++)
            v[ni] = __ldg((const float4*)(z + nidx[ni] * 64 + h * 32 + ch * 4));
        #pragma unroll
        for (int o = 0; o < 4; o++)
            w[o] = *(const float4*)&sW[wb][jb + 8 * o][ro + ch * 4];
        #pragma unroll
        for (int ni = 0; ni < 4; ni++)
            #pragma unroll
            for (int o = 0; o < 4; o++) {
                acc[ni][o] = fmaf(v[ni].x, w[o].x, acc[ni][o]);
                acc[ni][o] = fmaf(v[ni].y, w[o].y, acc[ni][o]);
                acc[ni][o] = fmaf(v[ni].z, w[o].z, acc[ni][o]);
                acc[ni][o] = fmaf(v[ni].w, w[o].w, acc[ni][o]);
            }
    }

    #pragma unroll
    for (int ni = 0; ni < 4; ni++) {
        int n = nbase + ni;
        if (n < N_NODES) {
            #pragma unroll
            for (int o = 0; o < 4; o++)
                g_zT[n * 128 + q * 32 + jb + 8 * o] = __float2half_rn(acc[ni][o]);
        }
    }
}

// ---------------- linear2: out = tanh(agg2P*invP + agg2N*invN + z_self@Wself + b) ----------------
#define KS2 36
__global__ void __launch_bounds__(256, 4)
linear2_lite(const float* __restrict__ w2b, const float* __restrict__ b2b,
             const float* __restrict__ w2u, const float* __restrict__ b2u,
             float* __restrict__ out)
{
    __shared__ float sW[2][32][KS2];   // self rows 64:95
    __shared__ float sB[64];
    int tid = threadIdx.x;
    for (int i = tid; i < 32 * 32; i += 256) {
        int k = i >> 5, j = i & 31;
        sW[0][j][k] = w2b[2048 + i];
        sW[1][j][k] = w2u[2048 + i];
    }
    if (tid < 32) { sB[tid] = b2b[tid]; sB[tid + 32] = b2u[tid]; }
    __syncthreads();

    int jg = tid & 15, ng = tid >> 4;
    int branch = jg >> 3, jb = jg & 7;
    int nbase = blockIdx.x * 64 + ng * 4;
    int nidx[4];
    #pragma unroll
    for (int ni = 0; ni < 4; ni++) {
        int n = nbase + ni; if (n > N_NODES - 1) n = N_NODES - 1;
        nidx[ni] = n;
    }

    const float* z = (const float*)g_z;
    float acc[4][4];
    #pragma unroll
    for (int ni = 0; ni < 4; ni++)
        #pragma unroll
        for (int o = 0; o < 4; o++)
            acc[ni][o] = sB[branch * 32 + jb + 8 * o];

    #pragma unroll
    for (int ch = 0; ch < 8; ch++) {
        float4 v[4], w[4];
        #pragma unroll
        for (int ni = 0; ni < 4; ni++)
            v[ni] = __ldg((const float4*)(z + nidx[ni] * 64 + branch * 32 + ch * 4));
        #pragma unroll
        for (int o = 0; o < 4; o++)
            w[o] = *(const float4*)&sW[branch][jb + 8 * o][ch * 4];
        #pragma unroll
        for (int ni = 0; ni < 4; ni++)
            #pragma unroll
            for (int o = 0; o < 4; o++) {
                acc[ni][o] = fmaf(v[ni].x, w[o].x, acc[ni][o]);
                acc[ni][o] = fmaf(v[ni].y, w[o].y, acc[ni][o]);
                acc[ni][o] = fmaf(v[ni].z, w[o].z, acc[ni][o]);
                acc[ni][o] = fmaf(v[ni].w, w[o].w, acc[ni][o]);
            }
    }

    #pragma unroll
    for (int ni = 0; ni < 4; ni++) {
        int n = nbase + ni;
        if (n < N_NODES) {
            float invP = 1.0f / fmaxf(g_cntP[n], 1.0f);
            float invN = 1.0f / fmaxf(g_cntN[n], 1.0f);
            #pragma unroll
            for (int o = 0; o < 4; o++) {
                int j = branch * 32 + jb + 8 * o;
                float au = __half2float(g_agg2P[n * 64 + j]);
                float av = __half2float(g_agg2N[n * 64 + j]);
                out[n * 64 + j] = ftanh(acc[ni][o] + au * invP + av * invN);
            }
        }
    }
}

// ---------------- launch ----------------
extern "C" void kernel_launch(void* const* d_in, const int* in_sizes, int n_in,
                              void* d_out, int out_size)
{
    const float* x    = (const float*)d_in[0];
    const int* posEI  = (const int*)d_in[1];
    const int* negEI  = (const int*)d_in[2];
    const float* w1b  = (const float*)d_in[3];
    const float* b1b  = (const float*)d_in[4];
    const float* w1u  = (const float*)d_in[5];
    const float* b1u  = (const float*)d_in[6];
    const float* w2b  = (const float*)d_in[7];
    const float* b2b  = (const float*)d_in[8];
    const float* w2u  = (const float*)d_in[9];
    const float* b2u  = (const float*)d_in[10];
    float* out = (float*)d_out;

    int E = in_sizes[1] / 2;             // 1,600,000
    const int* posSrc = posEI;
    const int* posDst = posEI + E;
    const int* negSrc = negEI;
    const int* negDst = negEI + E;

    int agg1Grid  = (E * 16 + 255) / 256;   // pos+neg merged
    int agg2Grid  = (E * 16 + 255) / 256;   // pos+neg merged, 8 threads/edge
    int lin64Grid = (N_NODES + 63) / 64;    // 1563
    int lin32Grid = (N_NODES + 31) / 32;    // 3125

    // --- layer 1 ---
    transform1_kernel<<<lin64Grid, 256>>>(x, w1b, w1u);
    agg1_kernel<<<agg1Grid, 256>>>(posSrc, posDst, negSrc, negDst, E);
    linear1_lite<<<lin64Grid, 256>>>(x, w1b, b1b, w1u, b1u);

    // --- layer 2 ---
    transform2_kernel<<<lin32Grid, 256>>>(w2b, w2u);
    agg2_kernel<<<agg2Grid, 256>>>(posSrc, posDst, negSrc, negDst, E);
    linear2_lite<<<lin64Grid, 256>>>(w2b, b2b, w2u, b2u, out);
}

// round 17
// speedup vs baseline: 1.4982x; 1.1457x over previous
#include <cuda_runtime.h>
#include <cuda_fp16.h>
#include <math.h>

#define N_NODES 100000
#define IN_DIM 64
#define HALF 32

// ---------------- scratch (device globals: allocation-free) ----------------
__device__ __half g_xT[N_NODES * 64];     // fp16 [x@W1b_agg | x@W1u_agg]
__device__ __half g_agg1P[N_NODES * 32];  // fp16 32-dim agg over pos
__device__ __half g_agg1N[N_NODES * 32];  // fp16 32-dim agg over neg
__device__ float4 g_z[N_NODES * 16];      // layer-1 output, f32
__device__ __half g_zT[N_NODES * 128];    // fp16 [u | v]
__device__ __half g_agg2P[N_NODES * 64];  // fp16 64-dim agg of u over pos
__device__ __half g_agg2N[N_NODES * 64];  // fp16 64-dim agg of v over neg
__device__ float  g_cntP[N_NODES];
__device__ float  g_cntN[N_NODES];

__device__ __forceinline__ float ftanh(float v) {
    float e = __expf(2.0f * v);
    return 1.0f - 2.0f / (e + 1.0f);
}

// ---------------- layer-1 aggregation: merged pos+neg, fp16 16B gather, one f16x2 red.v4/thread ----------------
// 4 threads/edge, each 8 dims. pos: xT cols 0:32, neg: 32:64.
__global__ void __launch_bounds__(256)
agg1_kernel(const int* __restrict__ posSrc, const int* __restrict__ posDst,
            const int* __restrict__ negSrc, const int* __restrict__ negDst, int E)
{
    int t = blockIdx.x * blockDim.x + threadIdx.x;
    if (t >= E * 8) return;
    int isNeg = (t >= E * 4);
    int tt = isNeg ? t - E * 4 : t;
    int e = tt >> 2, c = tt & 3;
    const int* src = isNeg ? negSrc : posSrc;
    const int* dst = isNeg ? negDst : posDst;
    int s = __ldg(src + e);
    int d = __ldg(dst + e);
    uint4 pv = __ldg((const uint4*)(g_xT + s * 64 + isNeg * 32) + c);
    __half* p = (isNeg ? g_agg1N : g_agg1P) + d * 32 + c * 8;
    asm volatile("red.global.add.noftz.v4.f16x2 [%0], {%1,%2,%3,%4};"
                 :: "l"(p), "r"(pv.x), "r"(pv.y), "r"(pv.z), "r"(pv.w) : "memory");
    if (c == 0) atomicAdd((isNeg ? g_cntN : g_cntP) + d, 1.0f);
}

// ---------------- layer-2 aggregation: merged pos+neg, fp16 16B gather, one f16x2 red.v4/thread ----------------
// 8 threads/edge, each 8 dims. pos: zT cols 0:64 (u), neg: 64:128 (v).
__global__ void __launch_bounds__(256)
agg2_kernel(const int* __restrict__ posSrc, const int* __restrict__ posDst,
            const int* __restrict__ negSrc, const int* __restrict__ negDst, int E)
{
    int t = blockIdx.x * blockDim.x + threadIdx.x;
    if (t >= E * 16) return;
    int isNeg = (t >= E * 8);
    int tt = isNeg ? t - E * 8 : t;
    int e = tt >> 3, c = tt & 7;
    const int* src = isNeg ? negSrc : posSrc;
    const int* dst = isNeg ? negDst : posDst;
    int s = __ldg(src + e);
    int d = __ldg(dst + e);
    uint4 pv = __ldg((const uint4*)(g_zT + s * 128 + isNeg * 64) + c);
    __half* p = (isNeg ? g_agg2N : g_agg2P) + d * 64 + c * 8;
    asm volatile("red.global.add.noftz.v4.f16x2 [%0], {%1,%2,%3,%4};"
                 :: "l"(p), "r"(pv.x), "r"(pv.y), "r"(pv.z), "r"(pv.w) : "memory");
}

// ---------------- transform1: xT = [x@w1b(rows 0:64) | x@w1u(rows 0:64)] (fp16 out) + zero agg1 ----------------
#define KS1 68
__global__ void __launch_bounds__(256, 4)
transform1_kernel(const float* __restrict__ x,
                  const float* __restrict__ w1b, const float* __restrict__ w1u)
{
    __shared__ float sW[2][32][KS1];
    int tid = threadIdx.x;
    for (int i = tid; i < 64 * 32; i += 256) {
        int k = i >> 5, j = i & 31;
        sW[0][j][k] = w1b[i];
        sW[1][j][k] = w1u[i];
    }

    // zero this block's agg1 rows + counts (64 nodes x 4 uint4 per buffer)
    int nbase0 = blockIdx.x * 64;
    uint4 z4 = make_uint4(0u, 0u, 0u, 0u);
    for (int i = tid; i < 256; i += 256) {
        int idx = nbase0 * 4 + i;
        if (idx < N_NODES * 4) {
            ((uint4*)g_agg1P)[idx] = z4;
            ((uint4*)g_agg1N)[idx] = z4;
        }
    }
    if (tid < 64) {
        int n = nbase0 + tid;
        if (n < N_NODES) { g_cntP[n] = 0.f; g_cntN[n] = 0.f; }
    }
    __syncthreads();

    int jg = tid & 15, ng = tid >> 4;
    int branch = jg >> 3, jb = jg & 7;
    int nbase = nbase0 + ng * 4;
    int nidx[4];
    #pragma unroll
    for (int ni = 0; ni < 4; ni++) {
        int n = nbase + ni; if (n > N_NODES - 1) n = N_NODES - 1;
        nidx[ni] = n;
    }

    float acc[4][4];
    #pragma unroll
    for (int ni = 0; ni < 4; ni++)
        #pragma unroll
        for (int o = 0; o < 4; o++) acc[ni][o] = 0.f;

    #pragma unroll 4
    for (int ch = 0; ch < 16; ch++) {
        float4 v[4], w[4];
        #pragma unroll
        for (int ni = 0; ni < 4; ni++)
            v[ni] = __ldg((const float4*)(x + nidx[ni] * 64 + ch * 4));
        #pragma unroll
        for (int o = 0; o < 4; o++)
            w[o] = *(const float4*)&sW[branch][jb + 8 * o][ch * 4];
        #pragma unroll
        for (int ni = 0; ni < 4; ni++)
            #pragma unroll
            for (int o = 0; o < 4; o++) {
                acc[ni][o] = fmaf(v[ni].x, w[o].x, acc[ni][o]);
                acc[ni][o] = fmaf(v[ni].y, w[o].y, acc[ni][o]);
                acc[ni][o] = fmaf(v[ni].z, w[o].z, acc[ni][o]);
                acc[ni][o] = fmaf(v[ni].w, w[o].w, acc[ni][o]);
            }
    }

    #pragma unroll
    for (int ni = 0; ni < 4; ni++) {
        int n = nbase + ni;
        if (n < N_NODES) {
            #pragma unroll
            for (int o = 0; o < 4; o++)
                g_xT[n * 64 + branch * 32 + jb + 8 * o] = __float2half_rn(acc[ni][o]);
        }
    }
}

// ---------------- linear1: z = tanh(agg1*inv + x@Wself + b) ----------------
__global__ void __launch_bounds__(256, 4)
linear1_lite(const float* __restrict__ x,
             const float* __restrict__ w1b, const float* __restrict__ b1b,
             const float* __restrict__ w1u, const float* __restrict__ b1u)
{
    __shared__ float sW[2][32][KS1];   // self rows 64:127
    __shared__ float sB[64];
    int tid = threadIdx.x;
    for (int i = tid; i < 64 * 32; i += 256) {
        int k = i >> 5, j = i & 31;
        sW[0][j][k] = w1b[2048 + i];
        sW[1][j][k] = w1u[2048 + i];
    }
    if (tid < 32) { sB[tid] = b1b[tid]; sB[tid + 32] = b1u[tid]; }
    __syncthreads();

    int jg = tid & 15, ng = tid >> 4;
    int branch = jg >> 3, jb = jg & 7;
    int nbase = blockIdx.x * 64 + ng * 4;
    int nidx[4];
    #pragma unroll
    for (int ni = 0; ni < 4; ni++) {
        int n = nbase + ni; if (n > N_NODES - 1) n = N_NODES - 1;
        nidx[ni] = n;
    }

    float acc[4][4];
    #pragma unroll
    for (int ni = 0; ni < 4; ni++)
        #pragma unroll
        for (int o = 0; o < 4; o++)
            acc[ni][o] = sB[branch * 32 + jb + 8 * o];

    #pragma unroll 4
    for (int ch = 0; ch < 16; ch++) {
        float4 v[4], w[4];
        #pragma unroll
        for (int ni = 0; ni < 4; ni++)
            v[ni] = __ldg((const float4*)(x + nidx[ni] * 64 + ch * 4));
        #pragma unroll
        for (int o = 0; o < 4; o++)
            w[o] = *(const float4*)&sW[branch][jb + 8 * o][ch * 4];
        #pragma unroll
        for (int ni = 0; ni < 4; ni++)
            #pragma unroll
            for (int o = 0; o < 4; o++) {
                acc[ni][o] = fmaf(v[ni].x, w[o].x, acc[ni][o]);
                acc[ni][o] = fmaf(v[ni].y, w[o].y, acc[ni][o]);
                acc[ni][o] = fmaf(v[ni].z, w[o].z, acc[ni][o]);
                acc[ni][o] = fmaf(v[ni].w, w[o].w, acc[ni][o]);
            }
    }

    const __half* agg = branch ? g_agg1N : g_agg1P;
    const float* cnt = branch ? g_cntN : g_cntP;
    float* zout = (float*)g_z;
    #pragma unroll
    for (int ni = 0; ni < 4; ni++) {
        int n = nbase + ni;
        if (n < N_NODES) {
            float inv = 1.0f / fmaxf(cnt[n], 1.0f);
            #pragma unroll
            for (int o = 0; o < 4; o++) {
                float a = __half2float(agg[n * 32 + jb + 8 * o]);
                zout[n * 64 + branch * 32 + jb + 8 * o] = ftanh(acc[ni][o] + a * inv);
            }
        }
    }
}

// ---------------- transform2: zT = [u | v] (fp16 out) + zero agg2 (fp16) ----------------
// u[0:32]=zp@w2b[0:32]   u[32:64]=zn@w2u[0:32]
// v[0:32]=zn@w2b[32:64]  v[32:64]=zp@w2u[32:64]
__global__ void __launch_bounds__(256, 4)
transform2_kernel(const float* __restrict__ w2b, const float* __restrict__ w2u)
{
    __shared__ float sW[2][32][KS1];   // w2b/w2u rows 0:64
    int tid = threadIdx.x;
    for (int i = tid; i < 64 * 32; i += 256) {
        int k = i >> 5, j = i & 31;
        sW[0][j][k] = w2b[i];
        sW[1][j][k] = w2u[i];
    }

    // zero this block's agg2 rows (32 nodes x 8 uint4 per buffer)
    int nbase0 = blockIdx.x * 32;
    uint4 z4 = make_uint4(0u, 0u, 0u, 0u);
    for (int i = tid; i < 256; i += 256) {
        int idx = nbase0 * 8 + i;
        if (idx < N_NODES * 8) {
            ((uint4*)g_agg2P)[idx] = z4;
            ((uint4*)g_agg2N)[idx] = z4;
        }
    }
    __syncthreads();

    int jg = tid & 31, ng = tid >> 5;
    int q = jg >> 3, jb = jg & 7;
    int h  = (q == 1 || q == 2) ? 1 : 0;
    int wb = (q == 0 || q == 2) ? 0 : 1;
    int ro = (q >= 2) ? 32 : 0;
    int nbase = nbase0 + ng * 4;
    int nidx[4];
    #pragma unroll
    for (int ni = 0; ni < 4; ni++) {
        int n = nbase + ni; if (n > N_NODES - 1) n = N_NODES - 1;
        nidx[ni] = n;
    }

    const float* z = (const float*)g_z;
    float acc[4][4];
    #pragma unroll
    for (int ni = 0; ni < 4; ni++)
        #pragma unroll
        for (int o = 0; o < 4; o++) acc[ni][o] = 0.f;

    #pragma unroll
    for (int ch = 0; ch < 8; ch++) {
        float4 v[4], w[4];
        #pragma unroll
        for (int ni = 0; ni < 4; ni++)
            v[ni] = __ldg((const float4*)(z + nidx[ni] * 64 + h * 32 + ch * 4));
        #pragma unroll
        for (int o = 0; o < 4; o++)
            w[o] = *(const float4*)&sW[wb][jb + 8 * o][ro + ch * 4];
        #pragma unroll
        for (int ni = 0; ni < 4; ni++)
            #pragma unroll
            for (int o = 0; o < 4; o++) {
                acc[ni][o] = fmaf(v[ni].x, w[o].x, acc[ni][o]);
                acc[ni][o] = fmaf(v[ni].y, w[o].y, acc[ni][o]);
                acc[ni][o] = fmaf(v[ni].z, w[o].z, acc[ni][o]);
                acc[ni][o] = fmaf(v[ni].w, w[o].w, acc[ni][o]);
            }
    }

    #pragma unroll
    for (int ni = 0; ni < 4; ni++) {
        int n = nbase + ni;
        if (n < N_NODES) {
            #pragma unroll
            for (int o = 0; o < 4; o++)
                g_zT[n * 128 + q * 32 + jb + 8 * o] = __float2half_rn(acc[ni][o]);
        }
    }
}

// ---------------- linear2: out = tanh(agg2P*invP + agg2N*invN + z_self@Wself + b) ----------------
#define KS2 36
__global__ void __launch_bounds__(256, 4)
linear2_lite(const float* __restrict__ w2b, const float* __restrict__ b2b,
             const float* __restrict__ w2u, const float* __restrict__ b2u,
             float* __restrict__ out)
{
    __shared__ float sW[2][32][KS2];   // self rows 64:95
    __shared__ float sB[64];
    int tid = threadIdx.x;
    for (int i = tid; i < 32 * 32; i += 256) {
        int k = i >> 5, j = i & 31;
        sW[0][j][k] = w2b[2048 + i];
        sW[1][j][k] = w2u[2048 + i];
    }
    if (tid < 32) { sB[tid] = b2b[tid]; sB[tid + 32] = b2u[tid]; }
    __syncthreads();

    int jg = tid & 15, ng = tid >> 4;
    int branch = jg >> 3, jb = jg & 7;
    int nbase = blockIdx.x * 64 + ng * 4;
    int nidx[4];
    #pragma unroll
    for (int ni = 0; ni < 4; ni++) {
        int n = nbase + ni; if (n > N_NODES - 1) n = N_NODES - 1;
        nidx[ni] = n;
    }

    const float* z = (const float*)g_z;
    float acc[4][4];
    #pragma unroll
    for (int ni = 0; ni < 4; ni++)
        #pragma unroll
        for (int o = 0; o < 4; o++)
            acc[ni][o] = sB[branch * 32 + jb + 8 * o];

    #pragma unroll
    for (int ch = 0; ch < 8; ch++) {
        float4 v[4], w[4];
        #pragma unroll
        for (int ni = 0; ni < 4; ni++)
            v[ni] = __ldg((const float4*)(z + nidx[ni] * 64 + branch * 32 + ch * 4));
        #pragma unroll
        for (int o = 0; o < 4; o++)
            w[o] = *(const float4*)&sW[branch][jb + 8 * o][ch * 4];
        #pragma unroll
        for (int ni = 0; ni < 4; ni++)
            #pragma unroll
            for (int o = 0; o < 4; o++) {
                acc[ni][o] = fmaf(v[ni].x, w[o].x, acc[ni][o]);
                acc[ni][o] = fmaf(v[ni].y, w[o].y, acc[ni][o]);
                acc[ni][o] = fmaf(v[ni].z, w[o].z, acc[ni][o]);
                acc[ni][o] = fmaf(v[ni].w, w[o].w, acc[ni][o]);
            }
    }

    #pragma unroll
    for (int ni = 0; ni < 4; ni++) {
        int n = nbase + ni;
        if (n < N_NODES) {
            float invP = 1.0f / fmaxf(g_cntP[n], 1.0f);
            float invN = 1.0f / fmaxf(g_cntN[n], 1.0f);
            #pragma unroll
            for (int o = 0; o < 4; o++) {
                int j = branch * 32 + jb + 8 * o;
                float au = __half2float(g_agg2P[n * 64 + j]);
                float av = __half2float(g_agg2N[n * 64 + j]);
                out[n * 64 + j] = ftanh(acc[ni][o] + au * invP + av * invN);
            }
        }
    }
}

// ---------------- launch ----------------
extern "C" void kernel_launch(void* const* d_in, const int* in_sizes, int n_in,
                              void* d_out, int out_size)
{
    const float* x    = (const float*)d_in[0];
    const int* posEI  = (const int*)d_in[1];
    const int* negEI  = (const int*)d_in[2];
    const float* w1b  = (const float*)d_in[3];
    const float* b1b  = (const float*)d_in[4];
    const float* w1u  = (const float*)d_in[5];
    const float* b1u  = (const float*)d_in[6];
    const float* w2b  = (const float*)d_in[7];
    const float* b2b  = (const float*)d_in[8];
    const float* w2u  = (const float*)d_in[9];
    const float* b2u  = (const float*)d_in[10];
    float* out = (float*)d_out;

    int E = in_sizes[1] / 2;             // 1,600,000
    const int* posSrc = posEI;
    const int* posDst = posEI + E;
    const int* negSrc = negEI;
    const int* negDst = negEI + E;

    int agg1Grid  = (E * 8 + 255) / 256;    // pos+neg merged, 4 threads/edge
    int agg2Grid  = (E * 16 + 255) / 256;   // pos+neg merged, 8 threads/edge
    int lin64Grid = (N_NODES + 63) / 64;    // 1563
    int lin32Grid = (N_NODES + 31) / 32;    // 3125

    // --- layer 1 ---
    transform1_kernel<<<lin64Grid, 256>>>(x, w1b, w1u);
    agg1_kernel<<<agg1Grid, 256>>>(posSrc, posDst, negSrc, negDst, E);
    linear1_lite<<<lin64Grid, 256>>>(x, w1b, b1b, w1u, b1u);

    // --- layer 2 ---
    transform2_kernel<<<lin32Grid, 256>>>(w2b, w2u);
    agg2_kernel<<<agg2Grid, 256>>>(posSrc, posDst, negSrc, negDst, E);
    linear2_lite<<<lin64Grid, 256>>>(w2b, b2b, w2u, b2u, out);
}